// round 12
// baseline (speedup 1.0000x reference)
#include <cuda_runtime.h>
#include <cuda_bf16.h>
#include <cstdint>

// ============================================================================
// LogMM: out[16384,1024] = log( x[16384,1024] @ matrix[1024,1024] )
// (reference's big/small branches sum exactly to log(max(y,tiny)))
//
// R12: crossbar relief. Measured: smem needs 138 B/cyc vs ~128 available at
// the 64x32 warp tile (per-MAC traffic ~ 1/Wm+1/Wn). Switch to 256x128 CTA
// tile, 8 warps 4x2, warp tile 64x64: 84 B/cyc needed -> tensor pipe unbinds.
// 1 CTA/SM (145KB smem), 256 threads, launch_bounds(256,1) for reg headroom,
// static wave scheduling (measured best), 3-stage cp.async ring.
// ============================================================================

#define M_TOTAL 16384
#define N_TOTAL 1024
#define K_TOTAL 1024
#define TILE_M 256
#define TILE_N 128
#define BK 64                    // bf16 per K-chunk (128 B per row)
#define NCHUNK (K_TOTAL / BK)    // 16
#define NSTAGE 3

static constexpr int SMEM_PAD = 1024;
static constexpr int A_TILE_BYTES = TILE_M * 128;   // 32768
static constexpr int B_TILE_BYTES = TILE_N * 128;   // 16384
static constexpr int BUF_STRIDE = A_TILE_BYTES + B_TILE_BYTES;  // 49152
static constexpr int SMEM_TOTAL = SMEM_PAD + NSTAGE * BUF_STRIDE;  // 148480

// Scratch bf16 buffers (device globals: allocation-free)
__device__ __align__(256) __nv_bfloat16 g_xb[(size_t)M_TOTAL * K_TOTAL];
__device__ __align__(256) __nv_bfloat16 g_bt[(size_t)N_TOTAL * K_TOTAL];

// ---------------------------------------------------------------------------
// Helpers
// ---------------------------------------------------------------------------
__device__ __forceinline__ uint32_t smem_u32(const void* p) {
    uint32_t a;
    asm("{ .reg .u64 t; cvta.to.shared.u64 t, %1; cvt.u32.u64 %0, t; }" : "=r"(a) : "l"(p));
    return a;
}
__device__ __forceinline__ uint32_t sw128(uint32_t off) {
    return off ^ ((off >> 3) & 0x70);
}
__device__ __forceinline__ void cp_async16(uint32_t smem_addr, const void* gptr) {
    asm volatile("cp.async.cg.shared.global [%0], [%1], 16;"
                 :: "r"(smem_addr), "l"(gptr) : "memory");
}
#define CP_COMMIT() asm volatile("cp.async.commit_group;" ::: "memory")
#define CP_WAIT(n)  asm volatile("cp.async.wait_group %0;" :: "n"(n) : "memory")

__device__ __forceinline__ void ldsm_x4(uint32_t* r, uint32_t addr) {
    asm volatile("ldmatrix.sync.aligned.m8n8.x4.shared.b16 {%0, %1, %2, %3}, [%4];"
                 : "=r"(r[0]), "=r"(r[1]), "=r"(r[2]), "=r"(r[3]) : "r"(addr));
}
__device__ __forceinline__ void mma16816(float* c, const uint32_t* a, const uint32_t* b) {
    asm volatile("mma.sync.aligned.m16n8k16.row.col.f32.bf16.bf16.f32 "
                 "{%0, %1, %2, %3}, {%4, %5, %6, %7}, {%8, %9}, {%0, %1, %2, %3};"
                 : "+f"(c[0]), "+f"(c[1]), "+f"(c[2]), "+f"(c[3])
                 : "r"(a[0]), "r"(a[1]), "r"(a[2]), "r"(a[3]), "r"(b[0]), "r"(b[1]));
}
__device__ __forceinline__ uint32_t pack_bf16x2(float a, float b) {
    __nv_bfloat162 h = __floats2bfloat162_rn(a, b);
    return *reinterpret_cast<uint32_t*>(&h);
}

// ---------------------------------------------------------------------------
// Fused conversion kernel (single launch):
//   blocks [0, 8192):         x fp32 -> g_xb bf16 (8 elems/thread)
//   blocks [8192, 8192+1024): matrix[K,N] -> g_bt[N,K] bf16 (32x32 tiles)
// ---------------------------------------------------------------------------
#define CVT_X_BLOCKS (M_TOTAL * K_TOTAL / (256 * 8))   // 8192
#define CVT_T_BLOCKS ((K_TOTAL / 32) * (N_TOTAL / 32)) // 1024

__global__ void __launch_bounds__(256)
cvt_kernel(const float* __restrict__ x, const float* __restrict__ m) {
    int tid = threadIdx.x;
    if (blockIdx.x < CVT_X_BLOCKS) {
        size_t i = ((size_t)blockIdx.x * 256 + tid) * 8;
        float4 a = *reinterpret_cast<const float4*>(x + i);
        float4 b = *reinterpret_cast<const float4*>(x + i + 4);
        uint4 o;
        o.x = pack_bf16x2(a.x, a.y);
        o.y = pack_bf16x2(a.z, a.w);
        o.z = pack_bf16x2(b.x, b.y);
        o.w = pack_bf16x2(b.z, b.w);
        *reinterpret_cast<uint4*>(g_xb + i) = o;
    } else {
        __shared__ float tile[32][33];
        int t = blockIdx.x - CVT_X_BLOCKS;
        int bn = (t & 31) * 32;          // n block
        int bk = (t >> 5) * 32;          // k block
        int lane = tid & 31;
        int rr = tid >> 5;               // 0..7
#pragma unroll
        for (int i = 0; i < 4; i++) {
            int row = i * 8 + rr;        // k within tile
            tile[row][lane] = m[(size_t)(bk + row) * N_TOTAL + bn + lane];
        }
        __syncthreads();
#pragma unroll
        for (int i = 0; i < 4; i++) {
            int row = i * 8 + rr;        // n within tile
            g_bt[(size_t)(bn + row) * K_TOTAL + bk + lane] =
                __float2bfloat16_rn(tile[lane][row]);
        }
    }
}

// ---------------------------------------------------------------------------
// GEMM + log kernel: 256x128 CTA tile, 64x64 warp tiles
// ---------------------------------------------------------------------------
__device__ __forceinline__ void load_tiles_async(uint32_t smem_base, int buf, int kc,
                                                 int m0, int n0, int tid) {
    const uint4* Ag = reinterpret_cast<const uint4*>(g_xb + (size_t)m0 * K_TOTAL + kc * BK);
    const uint4* Bg = reinterpret_cast<const uint4*>(g_bt + (size_t)n0 * K_TOTAL + kc * BK);
    uint32_t Abase = smem_base + SMEM_PAD + buf * BUF_STRIDE;
    uint32_t Bbase = Abase + A_TILE_BYTES;
    // A: 256 rows x 128B = 2048 16B-chunks (8/thread)
#pragma unroll
    for (int i = 0; i < 8; i++) {
        int cc = i * 256 + tid;
        int row = cc >> 3;                // 0..255
        int c16 = cc & 7;
        uint32_t sw = sw128((uint32_t)(row * 128 + c16 * 16));
        cp_async16(Abase + sw, Ag + (size_t)row * (K_TOTAL / 8) + c16);
    }
    // B: 128 rows x 128B = 1024 16B-chunks (4/thread)
#pragma unroll
    for (int i = 0; i < 4; i++) {
        int cc = i * 256 + tid;
        int row = cc >> 3;                // 0..127
        int c16 = cc & 7;
        uint32_t sw = sw128((uint32_t)(row * 128 + c16 * 16));
        cp_async16(Bbase + sw, Bg + (size_t)row * (K_TOTAL / 8) + c16);
    }
    CP_COMMIT();
}

__global__ void __launch_bounds__(256, 1)
logmm_gemm_kernel(float* __restrict__ out) {
    extern __shared__ char smem[];
    uint32_t sb = smem_u32(smem);
    int tid = threadIdx.x;
    int wid = tid >> 5;
    int lid = tid & 31;
    int n0 = blockIdx.x * TILE_N;
    int m0 = blockIdx.y * TILE_M;

    // 8 warps, 4x2: warp_m in {0..3} (64 rows), warp_n in {0,1} (64 cols)
    int warp_m = wid >> 1;
    int warp_n = wid & 1;

    float acc[4][8][4];    // mf (m16) x nf (n8) x frag = 128 regs
#pragma unroll
    for (int mf = 0; mf < 4; mf++)
#pragma unroll
        for (int nf = 0; nf < 8; nf++)
#pragma unroll
            for (int i = 0; i < 4; i++) acc[mf][nf][i] = 0.0f;

    // Prologue: fill 2 of 3 stages
    load_tiles_async(sb, 0, 0, m0, n0, tid);
    load_tiles_async(sb, 1, 1, m0, n0, tid);

    // Per-lane ldsm address components
    int a_row_l = lid & 15;
    int a_kb_l  = (lid >> 4) << 4;
    int b_row_l = (lid & 7) + ((lid >> 4) << 3);
    int b_kb_l  = ((lid >> 3) & 1) << 4;

    for (int c = 0; c < NCHUNK; c++) {
        if (c == NCHUNK - 1) { CP_WAIT(0); } else { CP_WAIT(1); }
        __syncthreads();

        if (c + 2 < NCHUNK) load_tiles_async(sb, (c + 2) % NSTAGE, c + 2, m0, n0, tid);

        uint32_t Ab = sb + SMEM_PAD + (c % NSTAGE) * BUF_STRIDE;
        uint32_t Bb = Ab + A_TILE_BYTES;
#pragma unroll
        for (int ks = 0; ks < 4; ks++) {
            uint32_t a[4][4], b[4][4];
#pragma unroll
            for (int mf = 0; mf < 4; mf++) {
                int row = warp_m * 64 + mf * 16 + a_row_l;
                uint32_t off = (uint32_t)(row * 128 + ks * 32 + a_kb_l);
                ldsm_x4(a[mf], Ab + sw128(off));
            }
#pragma unroll
            for (int p = 0; p < 4; p++) {
                int row = warp_n * 64 + p * 16 + b_row_l;
                uint32_t off = (uint32_t)(row * 128 + ks * 32 + b_kb_l);
                ldsm_x4(b[p], Bb + sw128(off));
            }
#pragma unroll
            for (int mf = 0; mf < 4; mf++)
#pragma unroll
                for (int nf = 0; nf < 8; nf++)
                    mma16816(acc[mf][nf], a[mf], b[nf >> 1] + (nf & 1) * 2);
        }
    }

    // Epilogue: log + store (frag: c0,c1 row lid/4; c2,c3 row lid/4+8)
#pragma unroll
    for (int mf = 0; mf < 4; mf++) {
#pragma unroll
        for (int nf = 0; nf < 8; nf++) {
            int row0 = m0 + warp_m * 64 + mf * 16 + (lid >> 2);
            int col = n0 + warp_n * 64 + nf * 8 + (lid & 3) * 2;
            float2 v0, v1;
            v0.x = __logf(fmaxf(acc[mf][nf][0], 1.17549435e-38f));
            v0.y = __logf(fmaxf(acc[mf][nf][1], 1.17549435e-38f));
            v1.x = __logf(fmaxf(acc[mf][nf][2], 1.17549435e-38f));
            v1.y = __logf(fmaxf(acc[mf][nf][3], 1.17549435e-38f));
            *reinterpret_cast<float2*>(out + (size_t)row0 * N_TOTAL + col) = v0;
            *reinterpret_cast<float2*>(out + (size_t)(row0 + 8) * N_TOTAL + col) = v1;
        }
    }
}

// ---------------------------------------------------------------------------
// Launch
// ---------------------------------------------------------------------------
extern "C" void kernel_launch(void* const* d_in, const int* in_sizes, int n_in,
                              void* d_out, int out_size) {
    const float* x = (const float*)d_in[0];
    const float* mat = (const float*)d_in[1];
    if (n_in >= 2 && in_sizes[0] == N_TOTAL * K_TOTAL && in_sizes[1] == M_TOTAL * K_TOTAL) {
        const float* t = x; x = mat; mat = t;
    }
    float* out = (float*)d_out;

    cudaFuncSetAttribute(logmm_gemm_kernel,
                         cudaFuncAttributeMaxDynamicSharedMemorySize, SMEM_TOTAL);

    cvt_kernel<<<CVT_X_BLOCKS + CVT_T_BLOCKS, 256>>>(x, mat);
    dim3 grid(N_TOTAL / TILE_N, M_TOTAL / TILE_M);  // (8, 64)
    logmm_gemm_kernel<<<grid, 256, SMEM_TOTAL>>>(out);
}